// round 1
// baseline (speedup 1.0000x reference)
#include <cuda_runtime.h>
#include <math.h>

// Problem constants
#define BN_  8192   // batch
#define DN_  2048   // feature dim
#define NI_  1023   // inner nodes
#define NL_  1024   // leaves (= padded inner node count)
#define CN_  1000   // classes

// ---------------- device-global scratch (no allocations allowed) ----------------
__device__ float g_Wp[DN_ * NL_];                 // W padded to [2048,1024], pad col = 0
__device__ float g_bp[NL_];                       // b padded to 1024, pad = 0
__device__ float g_dec[(size_t)BN_ * NL_];        // sigmoid(x@W+b), stride 1024
__device__ float g_pp[(size_t)BN_ * NL_];         // path probabilities, stride 1024
__device__ float g_lp[(size_t)NL_ * NL_];         // softmax(leaf_dist) padded to [1024,1024]

// ---------------- prep: pad W and b ----------------
__global__ void pad_w_kernel(const float* __restrict__ W, const float* __restrict__ b) {
    int idx = blockIdx.x * blockDim.x + threadIdx.x;
    if (idx < DN_ * NL_) {
        int r = idx >> 10;
        int c = idx & 1023;
        g_Wp[idx] = (c < NI_) ? W[r * NI_ + c] : 0.0f;
    }
    if (idx < NL_) g_bp[idx] = (idx < NI_) ? b[idx] : 0.0f;
}

// ---------------- softmax over leaf_dist rows, pad cols [1000,1024) with 0 ----------------
__global__ __launch_bounds__(256) void softmax_kernel(const float* __restrict__ ld) {
    int row = blockIdx.x;                       // 1024 rows
    const float* r = ld + (size_t)row * CN_;
    float*       o = g_lp + (size_t)row * NL_;
    __shared__ float sred[8];
    int tid = threadIdx.x;

    float mx = -3.4e38f;
    for (int i = tid; i < CN_; i += 256) mx = fmaxf(mx, r[i]);
    #pragma unroll
    for (int s = 16; s; s >>= 1) mx = fmaxf(mx, __shfl_xor_sync(0xffffffffu, mx, s));
    if ((tid & 31) == 0) sred[tid >> 5] = mx;
    __syncthreads();
    mx = sred[0];
    #pragma unroll
    for (int w = 1; w < 8; w++) mx = fmaxf(mx, sred[w]);
    __syncthreads();

    float sum = 0.0f;
    for (int i = tid; i < CN_; i += 256) sum += expf(r[i] - mx);
    #pragma unroll
    for (int s = 16; s; s >>= 1) sum += __shfl_xor_sync(0xffffffffu, sum, s);
    if ((tid & 31) == 0) sred[tid >> 5] = sum;
    __syncthreads();
    sum = 0.0f;
    #pragma unroll
    for (int w = 0; w < 8; w++) sum += sred[w];
    float inv = 1.0f / sum;

    for (int i = tid; i < CN_; i += 256) o[i] = expf(r[i] - mx) * inv;
    for (int i = CN_ + tid; i < NL_; i += 256) o[i] = 0.0f;
}

// ---------------- tree path-probability expansion (exact reference recurrence) ----------------
__global__ __launch_bounds__(256) void pp_kernel() {
    int row = blockIdx.x;                       // 8192 rows
    __shared__ float ds[NL_];
    __shared__ float buf0[NL_];
    __shared__ float buf1[NL_];
    int tid = threadIdx.x;

    const float* dr = g_dec + (size_t)row * NL_;
    for (int i = tid; i < NL_; i += 256) ds[i] = dr[i];
    if (tid == 0) buf0[0] = 1.0f;
    __syncthreads();

    float* cur = buf0;
    float* nxt = buf1;
    #pragma unroll
    for (int d = 0; d < 10; d++) {
        int L = 1 << d;
        for (int j = tid; j < 2 * L; j += 256) {
            // w[i]  = v[i mod L] * (i<L ? ld[i] : 1-ld[i-L]);  w' = concat(w[::2], w[1::2])
            int  i2   = (j < L) ? (2 * j) : (2 * (j - L) + 1);
            int  vi   = i2 & (L - 1);
            bool left = (i2 < L);
            int  node = (L - 1) + (left ? i2 : (i2 - L));
            float dd  = ds[node];
            nxt[j] = cur[vi] * (left ? dd : (1.0f - dd));
        }
        __syncthreads();
        float* t = cur; cur = nxt; nxt = t;
    }

    float* po = g_pp + (size_t)row * NL_;
    for (int i = tid; i < NL_; i += 256) po[i] = cur[i];
}

// ---------------- 128x128x16 fp32 SGEMM, 256 threads, 8x8 micro-tile ----------------
// C[M,N] = A[M,K] @ B[K,N] (+ bias, sigmoid if SIG). M,K multiples of 128/16; N = 128*gridDim.x
// stores guarded at col < nvalid (nvalid % 4 == 0).
template <bool SIG>
__global__ __launch_bounds__(256) void sgemm_kernel(
    const float* __restrict__ A, const float* __restrict__ Bm,
    const float* __restrict__ bias, float* __restrict__ C,
    int K, int lda, int ldb, int ldc, int nvalid)
{
    __shared__ float As[16][128];
    __shared__ float Bs[16][128];

    int tid = threadIdx.x;
    int tx = tid & 15;           // N direction (x8)
    int ty = tid >> 4;           // M direction (x8)
    int rowBase = blockIdx.y * 128;
    int colBase = blockIdx.x * 128;

    int arow = tid >> 2;             // 0..63
    int acol = (tid & 3) << 2;       // 0,4,8,12
    int brow = tid >> 5;             // 0..7
    int bcol = (tid & 31) << 2;      // 0..124

    const float* Aptr = A + (size_t)(rowBase + arow) * lda + acol;
    const float* Bptr = Bm + (size_t)brow * ldb + colBase + bcol;

    float acc[8][8];
    #pragma unroll
    for (int i = 0; i < 8; i++)
        #pragma unroll
        for (int j = 0; j < 8; j++) acc[i][j] = 0.0f;

    for (int kt = 0; kt < K; kt += 16) {
        float4 a0 = *(const float4*)(Aptr);
        float4 a1 = *(const float4*)(Aptr + (size_t)64 * lda);
        float4 b0 = *(const float4*)(Bptr);
        float4 b1 = *(const float4*)(Bptr + (size_t)8 * ldb);
        Aptr += 16;
        Bptr += (size_t)16 * ldb;

        As[acol + 0][arow] = a0.x;
        As[acol + 1][arow] = a0.y;
        As[acol + 2][arow] = a0.z;
        As[acol + 3][arow] = a0.w;
        As[acol + 0][arow + 64] = a1.x;
        As[acol + 1][arow + 64] = a1.y;
        As[acol + 2][arow + 64] = a1.z;
        As[acol + 3][arow + 64] = a1.w;
        *(float4*)&Bs[brow][bcol]     = b0;
        *(float4*)&Bs[brow + 8][bcol] = b1;
        __syncthreads();

        #pragma unroll
        for (int kk = 0; kk < 16; kk++) {
            float ar[8], br[8];
            *(float4*)&ar[0] = *(const float4*)&As[kk][ty * 8];
            *(float4*)&ar[4] = *(const float4*)&As[kk][ty * 8 + 4];
            *(float4*)&br[0] = *(const float4*)&Bs[kk][tx * 8];
            *(float4*)&br[4] = *(const float4*)&Bs[kk][tx * 8 + 4];
            #pragma unroll
            for (int i = 0; i < 8; i++)
                #pragma unroll
                for (int j = 0; j < 8; j++)
                    acc[i][j] += ar[i] * br[j];
        }
        __syncthreads();
    }

    #pragma unroll
    for (int i = 0; i < 8; i++) {
        int row = rowBase + ty * 8 + i;
        #pragma unroll
        for (int jj = 0; jj < 2; jj++) {
            int col = colBase + tx * 8 + jj * 4;
            float4 v;
            v.x = acc[i][jj * 4 + 0];
            v.y = acc[i][jj * 4 + 1];
            v.z = acc[i][jj * 4 + 2];
            v.w = acc[i][jj * 4 + 3];
            if (SIG) {
                v.x = 1.0f / (1.0f + expf(-(v.x + bias[col + 0])));
                v.y = 1.0f / (1.0f + expf(-(v.y + bias[col + 1])));
                v.z = 1.0f / (1.0f + expf(-(v.z + bias[col + 2])));
                v.w = 1.0f / (1.0f + expf(-(v.w + bias[col + 3])));
            }
            if (col < nvalid)
                *(float4*)(C + (size_t)row * ldc + col) = v;
        }
    }
}

// ---------------- launch ----------------
extern "C" void kernel_launch(void* const* d_in, const int* in_sizes, int n_in,
                              void* d_out, int out_size)
{
    const float* x    = (const float*)d_in[0];   // [8192, 2048]
    const float* W    = (const float*)d_in[1];   // [2048, 1023]
    const float* b    = (const float*)d_in[2];   // [1023]
    const float* leaf = (const float*)d_in[3];   // [1024, 1000]
    float*       out  = (float*)d_out;           // [8192, 1000]

    float *Wp, *bp, *dec, *pp, *lp;
    cudaGetSymbolAddress((void**)&Wp,  g_Wp);
    cudaGetSymbolAddress((void**)&bp,  g_bp);
    cudaGetSymbolAddress((void**)&dec, g_dec);
    cudaGetSymbolAddress((void**)&pp,  g_pp);
    cudaGetSymbolAddress((void**)&lp,  g_lp);

    // 1) pad W/b (removes odd stride 1023; pad col = 0 so no N-guard needed in GEMM1)
    pad_w_kernel<<<(DN_ * NL_ + 255) / 256, 256>>>(W, b);

    // 2) softmax of leaf_dist into padded [1024,1024] (pad cols zeroed)
    softmax_kernel<<<NL_, 256>>>(leaf);

    // 3) decisions = sigmoid(x @ Wp + bp)   [8192,1024]
    sgemm_kernel<true><<<dim3(NL_ / 128, BN_ / 128), 256>>>(
        x, Wp, bp, dec, DN_, DN_, NL_, NL_, NL_);

    // 4) tree expansion -> pp [8192,1024]
    pp_kernel<<<BN_, 256>>>();

    // 5) out = pp @ leafp   [8192,1000]  (stores guarded at col < 1000)
    sgemm_kernel<false><<<dim3(NL_ / 128, BN_ / 128), 256>>>(
        pp, lp, nullptr, out, NL_, NL_, NL_, CN_, CN_);
}

// round 3
// speedup vs baseline: 3.0768x; 3.0768x over previous
#include <cuda_runtime.h>
#include <stdint.h>
#include <math.h>

// ---------------- problem constants ----------------
#define BN_ 8192   // batch
#define DN_ 2048   // feature dim
#define NI_ 1023   // inner nodes
#define NL_ 1024   // leaves / padded inner count
#define CN_ 1000   // classes

// ---------------- device-global scratch ----------------
__device__ float g_WpT[NL_ * DN_];                // W^T padded, tf32-rounded: [1024 n][2048 k]
__device__ float g_bp[NL_];
__device__ float g_dec[(size_t)BN_ * NL_];        // decisions [8192][1024] (fp32)
__device__ float g_pp[(size_t)BN_ * NL_];         // path probs [8192][1024] (tf32-rounded)
__device__ float g_lp[NL_ * NL_];                 // softmax(leaf) [1024 leaf][1024 cls pad]
__device__ float g_lpT[NL_ * NL_];                // transposed, tf32-rounded [1024 cls][1024 leaf]

// ---------------- helpers ----------------
__device__ __forceinline__ uint32_t f2tf32(float f) {
    uint32_t u;
    asm("cvt.rna.tf32.f32 %0, %1;" : "=r"(u) : "f"(f));
    return u;
}
__device__ __forceinline__ uint32_t smem_u32(const void* p) {
    uint32_t a;
    asm("{ .reg .u64 t; cvta.to.shared.u64 t, %1; cvt.u32.u64 %0, t; }" : "=r"(a) : "l"(p));
    return a;
}
__device__ __forceinline__ void cpasync16(uint32_t dst, const float* src) {
    asm volatile("cp.async.cg.shared.global [%0], [%1], 16;" :: "r"(dst), "l"(src) : "memory");
}
__device__ __forceinline__ void mma816(float* d, const uint32_t* a, const uint32_t* b) {
    asm volatile("mma.sync.aligned.m16n8k8.row.col.f32.tf32.tf32.f32 "
        "{%0,%1,%2,%3}, {%4,%5,%6,%7}, {%8,%9}, {%0,%1,%2,%3};"
        : "+f"(d[0]), "+f"(d[1]), "+f"(d[2]), "+f"(d[3])
        : "r"(a[0]), "r"(a[1]), "r"(a[2]), "r"(a[3]), "r"(b[0]), "r"(b[1]));
}

// ---------------- prep kernels ----------------
__global__ void pad_b_kernel(const float* __restrict__ b) {
    int i = blockIdx.x * 256 + threadIdx.x;
    if (i < NL_) g_bp[i] = (i < NI_) ? b[i] : 0.0f;
}

// W [2048 k][1023 n] -> g_WpT [1024 n][2048 k] (tf32-rounded), pad n=1023 with 0
__global__ __launch_bounds__(256) void transpose_W(const float* __restrict__ W) {
    __shared__ float t[32][33];
    int k0 = blockIdx.x * 32, n0 = blockIdx.y * 32;
    int tx = threadIdx.x, ty = threadIdx.y;   // 32 x 8
    #pragma unroll
    for (int i = 0; i < 32; i += 8) {
        int n = n0 + tx;
        t[ty + i][tx] = (n < NI_) ? W[(size_t)(k0 + ty + i) * NI_ + n] : 0.0f;
    }
    __syncthreads();
    #pragma unroll
    for (int i = 0; i < 32; i += 8)
        g_WpT[(size_t)(n0 + ty + i) * DN_ + k0 + tx] = __uint_as_float(f2tf32(t[tx][ty + i]));
}

// softmax rows of leaf_dist [1024, 1000] -> g_lp [1024, 1024] (pad zeroed)
__global__ __launch_bounds__(256) void softmax_kernel(const float* __restrict__ ld) {
    int row = blockIdx.x;
    const float* r = ld + (size_t)row * CN_;
    float*       o = g_lp + (size_t)row * NL_;
    __shared__ float sred[8];
    int tid = threadIdx.x;

    float mx = -3.4e38f;
    for (int i = tid; i < CN_; i += 256) mx = fmaxf(mx, r[i]);
    #pragma unroll
    for (int s = 16; s; s >>= 1) mx = fmaxf(mx, __shfl_xor_sync(0xffffffffu, mx, s));
    if ((tid & 31) == 0) sred[tid >> 5] = mx;
    __syncthreads();
    mx = sred[0];
    #pragma unroll
    for (int w = 1; w < 8; w++) mx = fmaxf(mx, sred[w]);
    __syncthreads();

    float sum = 0.0f;
    for (int i = tid; i < CN_; i += 256) sum += expf(r[i] - mx);
    #pragma unroll
    for (int s = 16; s; s >>= 1) sum += __shfl_xor_sync(0xffffffffu, sum, s);
    if ((tid & 31) == 0) sred[tid >> 5] = sum;
    __syncthreads();
    sum = 0.0f;
    #pragma unroll
    for (int w = 0; w < 8; w++) sum += sred[w];
    float inv = 1.0f / sum;

    for (int i = tid; i < CN_; i += 256) o[i] = expf(r[i] - mx) * inv;
    for (int i = CN_ + tid; i < NL_; i += 256) o[i] = 0.0f;
}

// g_lp [leaf][cls] -> g_lpT [cls][leaf] (tf32-rounded)
__global__ __launch_bounds__(256) void transpose_lp() {
    __shared__ float t[32][33];
    int r0 = blockIdx.x * 32, c0 = blockIdx.y * 32;
    int tx = threadIdx.x, ty = threadIdx.y;
    #pragma unroll
    for (int i = 0; i < 32; i += 8)
        t[ty + i][tx] = g_lp[(size_t)(r0 + ty + i) * NL_ + c0 + tx];
    __syncthreads();
    #pragma unroll
    for (int i = 0; i < 32; i += 8)
        g_lpT[(size_t)(c0 + ty + i) * NL_ + r0 + tx] = __uint_as_float(f2tf32(t[tx][ty + i]));
}

// ---------------- tree path-probability expansion (verified recurrence) ----------------
__global__ __launch_bounds__(256) void pp_kernel() {
    int row = blockIdx.x;
    __shared__ float ds[NL_];
    __shared__ float buf0[NL_];
    __shared__ float buf1[NL_];
    int tid = threadIdx.x;

    const float* dr = g_dec + (size_t)row * NL_;
    for (int i = tid; i < NL_; i += 256) ds[i] = dr[i];
    if (tid == 0) buf0[0] = 1.0f;
    __syncthreads();

    float* cur = buf0;
    float* nxt = buf1;
    #pragma unroll
    for (int d = 0; d < 10; d++) {
        int L = 1 << d;
        for (int j = tid; j < 2 * L; j += 256) {
            int  i2   = (j < L) ? (2 * j) : (2 * (j - L) + 1);
            int  vi   = i2 & (L - 1);
            bool left = (i2 < L);
            int  node = (L - 1) + (left ? i2 : (i2 - L));
            float dd  = ds[node];
            nxt[j] = cur[vi] * (left ? dd : (1.0f - dd));
        }
        __syncthreads();
        float* t = cur; cur = nxt; nxt = t;
    }

    float* po = g_pp + (size_t)row * NL_;
    for (int i = tid; i < NL_; i += 256) po[i] = __uint_as_float(f2tf32(cur[i]));
}

// ---------------- tf32 mma.sync GEMM: 128x128x32, 3-stage cp.async, 4 warps ----------------
#define BM   128
#define BNT  128
#define BKT  32
#define STG  3
#define PADK 36                                  // floats per smem row (conflict-free frags)
#define SSTAGE ((BM + BNT) * PADK)               // floats per stage = 9216
#define SMEM_GEMM (STG * SSTAGE * 4)             // 110592 bytes

template <bool SIG>
__global__ __launch_bounds__(128, 2) void gemm_mma(
    const float* __restrict__ A, const float* __restrict__ Bm,
    const float* __restrict__ bias, float* __restrict__ C,
    int K, int lda, int ldb, int ldc, int nvalid)
{
    extern __shared__ float sm[];
    const int tid  = threadIdx.x;
    const int wid  = tid >> 5, lane = tid & 31;
    const int gid  = lane >> 2, tig = lane & 3;
    const int m0   = (wid & 1) * 64, n0 = (wid >> 1) * 64;
    const int rowBase = blockIdx.y * BM;
    const int colBase = blockIdx.x * BNT;
    const uint32_t sb = smem_u32(sm);

    const float* Ag = A + (size_t)rowBase * lda;
    const float* Bg = Bm + (size_t)colBase * ldb;

    float acc[4][8][4];
    #pragma unroll
    for (int mf = 0; mf < 4; mf++)
        #pragma unroll
        for (int nf = 0; nf < 8; nf++)
            #pragma unroll
            for (int q = 0; q < 4; q++) acc[mf][nf][q] = 0.0f;

    const int nkt = K / BKT;

    // stage loader: 8 A-chunks + 8 B-chunks (16B each) per thread
    auto load_stage = [&](int s, int kt) {
        uint32_t abase = sb + (uint32_t)(s * SSTAGE) * 4;
        uint32_t bbase = abase + BM * PADK * 4;
        const float* Ak = Ag + kt * BKT;
        const float* Bk = Bg + kt * BKT;
        #pragma unroll
        for (int i = 0; i < 8; i++) {
            int idx = tid + i * 128;
            int row = idx >> 3, kc = idx & 7;
            cpasync16(abase + (uint32_t)(row * PADK + kc * 4) * 4, Ak + (size_t)row * lda + kc * 4);
        }
        #pragma unroll
        for (int i = 0; i < 8; i++) {
            int idx = tid + i * 128;
            int row = idx >> 3, kc = idx & 7;
            cpasync16(bbase + (uint32_t)(row * PADK + kc * 4) * 4, Bk + (size_t)row * ldb + kc * 4);
        }
    };

    // prologue: 2 stages in flight
    load_stage(0, 0);
    asm volatile("cp.async.commit_group;" ::: "memory");
    load_stage(1, 1);
    asm volatile("cp.async.commit_group;" ::: "memory");

    int stage = 0;
    for (int kt = 0; kt < nkt; kt++) {
        asm volatile("cp.async.wait_group 1;" ::: "memory");
        __syncthreads();

        if (kt + 2 < nkt) {
            int s2 = stage + 2; if (s2 >= STG) s2 -= STG;
            load_stage(s2, kt + 2);
        }
        asm volatile("cp.async.commit_group;" ::: "memory");

        const float* as = sm + stage * SSTAGE;
        const float* bs = as + BM * PADK;
        #pragma unroll
        for (int ks = 0; ks < 4; ks++) {
            const int k = ks * 8;
            uint32_t a[4][4], b[8][2];
            #pragma unroll
            for (int mf = 0; mf < 4; mf++) {
                int r = m0 + mf * 16 + gid;
                a[mf][0] = f2tf32(as[r * PADK + k + tig]);
                a[mf][1] = f2tf32(as[(r + 8) * PADK + k + tig]);
                a[mf][2] = f2tf32(as[r * PADK + k + tig + 4]);
                a[mf][3] = f2tf32(as[(r + 8) * PADK + k + tig + 4]);
            }
            #pragma unroll
            for (int nf = 0; nf < 8; nf++) {
                int c = n0 + nf * 8 + gid;
                b[nf][0] = __float_as_uint(bs[c * PADK + k + tig]);
                b[nf][1] = __float_as_uint(bs[c * PADK + k + tig + 4]);
            }
            #pragma unroll
            for (int mf = 0; mf < 4; mf++)
                #pragma unroll
                for (int nf = 0; nf < 8; nf++)
                    mma816(acc[mf][nf], a[mf], b[nf]);
        }
        stage++; if (stage == STG) stage = 0;
    }

    // epilogue
    #pragma unroll
    for (int mf = 0; mf < 4; mf++) {
        int r0 = rowBase + m0 + mf * 16 + gid;
        #pragma unroll
        for (int nf = 0; nf < 8; nf++) {
            int col = colBase + n0 + nf * 8 + tig * 2;
            float2 v0 = make_float2(acc[mf][nf][0], acc[mf][nf][1]);
            float2 v1 = make_float2(acc[mf][nf][2], acc[mf][nf][3]);
            if (SIG) {
                float b0 = bias[col], b1 = bias[col + 1];
                v0.x = 1.0f / (1.0f + expf(-(v0.x + b0)));
                v0.y = 1.0f / (1.0f + expf(-(v0.y + b1)));
                v1.x = 1.0f / (1.0f + expf(-(v1.x + b0)));
                v1.y = 1.0f / (1.0f + expf(-(v1.y + b1)));
            }
            if (col < nvalid) {
                *(float2*)(C + (size_t)r0 * ldc + col) = v0;
                *(float2*)(C + (size_t)(r0 + 8) * ldc + col) = v1;
            }
        }
    }
}

// ---------------- host launch ----------------
extern "C" void kernel_launch(void* const* d_in, const int* in_sizes, int n_in,
                              void* d_out, int out_size)
{
    const float* x    = (const float*)d_in[0];   // [8192, 2048]
    const float* W    = (const float*)d_in[1];   // [2048, 1023]
    const float* b    = (const float*)d_in[2];   // [1023]
    const float* leaf = (const float*)d_in[3];   // [1024, 1000]
    float*       out  = (float*)d_out;           // [8192, 1000]

    float *WpT, *bp, *dec, *pp, *lpT;
    cudaGetSymbolAddress((void**)&WpT, g_WpT);
    cudaGetSymbolAddress((void**)&bp,  g_bp);
    cudaGetSymbolAddress((void**)&dec, g_dec);
    cudaGetSymbolAddress((void**)&pp,  g_pp);
    cudaGetSymbolAddress((void**)&lpT, g_lpT);

    static bool attr_set = false;
    if (!attr_set) {
        cudaFuncSetAttribute(gemm_mma<true>,  cudaFuncAttributeMaxDynamicSharedMemorySize, SMEM_GEMM);
        cudaFuncSetAttribute(gemm_mma<false>, cudaFuncAttributeMaxDynamicSharedMemorySize, SMEM_GEMM);
        attr_set = true;
    }

    // prep
    transpose_W<<<dim3(DN_ / 32, NL_ / 32), dim3(32, 8)>>>(W);
    pad_b_kernel<<<4, 256>>>(b);
    softmax_kernel<<<NL_, 256>>>(leaf);
    transpose_lp<<<dim3(32, 32), dim3(32, 8)>>>();

    // 1) decisions = sigmoid(x @ W + b)   [8192,1024]
    gemm_mma<true><<<dim3(NL_ / BNT, BN_ / BM), 128, SMEM_GEMM>>>(
        x, WpT, bp, dec, DN_, DN_, DN_, NL_, NL_);

    // 2) tree expansion -> pp [8192,1024] (tf32-rounded)
    pp_kernel<<<BN_, 256>>>();

    // 3) out = pp @ leaf_probs   [8192,1000]
    gemm_mma<false><<<dim3(NL_ / BNT, BN_ / BM), 128, SMEM_GEMM>>>(
        pp, lpT, nullptr, out, NL_, NL_, NL_, CN_, CN_);
}